// round 9
// baseline (speedup 1.0000x reference)
#include <cuda_runtime.h>
#include <cuda_fp16.h>
#include <cstdint>
#include <math.h>

#define DD 128
#define KK 32
#define NMAX 50000

// Scratch (allocation-free rule: __device__ globals)
__device__ float  g_x[NMAX * DD];     // tangent-space features for layer-1 GEMM
__device__ __half g_msg[NMAX * DD];   // GEMM output (messages), fp16

// ---------------------------------------------------------------------------
// cp.async 16B helper (pred=false -> zero-fill)
// ---------------------------------------------------------------------------
__device__ __forceinline__ void cp16(void* dst_smem, const void* src, bool pred) {
    unsigned sdst = (unsigned)__cvta_generic_to_shared(dst_smem);
    int sz = pred ? 16 : 0;
    asm volatile("cp.async.cg.shared.global [%0], [%1], 16, %2;\n"
                 :: "r"(sdst), "l"(src), "r"(sz));
}

// ---------------------------------------------------------------------------
// Tensor-core GEMM: C[N,128] = A @ W[128,128], epilogue * mask^MPOW, fp16 out.
// mma.sync.m16n8k8 tf32, fp32 accumulate. 2-stage cp.async pipeline, BK=16.
// ---------------------------------------------------------------------------
#define BK 16
#define SA 20
#define SW 136

template <int MPOW>
__global__ __launch_bounds__(256, 2)
void gemm_tc_kernel(const float* __restrict__ A,
                    const float* __restrict__ W,
                    const float* __restrict__ mask,
                    __half* __restrict__ C,
                    int N) {
    __shared__ float As[2][128 * SA];
    __shared__ float Ws[2][BK * SW];

    int tid  = threadIdx.x;
    int lane = tid & 31;
    int warp = tid >> 5;
    int wr   = warp >> 1;
    int wc   = warp & 1;
    int g    = lane >> 2;
    int tg   = lane & 3;

    int block_row = blockIdx.x * 128;

    float acc[2][8][4];
    #pragma unroll
    for (int ma = 0; ma < 2; ma++)
        #pragma unroll
        for (int na = 0; na < 8; na++)
            #pragma unroll
            for (int i = 0; i < 4; i++) acc[ma][na][i] = 0.f;

    #define LOAD_TILES(s, k0)                                                  \
    {                                                                          \
        _Pragma("unroll")                                                      \
        for (int i = 0; i < 2; i++) {                                          \
            int idx  = tid + i * 256;                                          \
            int row  = idx >> 2;                                               \
            int c4   = idx & 3;                                                \
            int grow = block_row + row;                                        \
            cp16(&As[s][row * SA + c4 * 4],                                    \
                 A + (size_t)grow * 128 + (k0) + c4 * 4, grow < N);            \
        }                                                                      \
        _Pragma("unroll")                                                      \
        for (int i = 0; i < 2; i++) {                                          \
            int idx = tid + i * 256;                                           \
            int kr  = idx >> 5;                                                \
            int c4  = idx & 31;                                                \
            cp16(&Ws[s][kr * SW + c4 * 4],                                     \
                 W + (size_t)((k0) + kr) * 128 + c4 * 4, true);                \
        }                                                                      \
        asm volatile("cp.async.commit_group;\n");                              \
    }

    LOAD_TILES(0, 0);

    #pragma unroll
    for (int it = 0; it < 8; it++) {
        int s = it & 1;
        if (it < 7) LOAD_TILES(s ^ 1, (it + 1) * BK);
        if (it < 7) asm volatile("cp.async.wait_group 1;\n");
        else        asm volatile("cp.async.wait_group 0;\n");
        __syncthreads();

        #pragma unroll
        for (int ks = 0; ks < 2; ks++) {
            int k8 = ks * 8;
            unsigned int af[2][4];
            #pragma unroll
            for (int ma = 0; ma < 2; ma++) {
                int r = wr * 32 + ma * 16;
                const unsigned int* Asu = (const unsigned int*)As[s];
                af[ma][0] = Asu[(r + g)     * SA + k8 + tg];
                af[ma][1] = Asu[(r + g + 8) * SA + k8 + tg];
                af[ma][2] = Asu[(r + g)     * SA + k8 + tg + 4];
                af[ma][3] = Asu[(r + g + 8) * SA + k8 + tg + 4];
            }
            unsigned int bf[8][2];
            #pragma unroll
            for (int na = 0; na < 8; na++) {
                int cc = wc * 64 + na * 8 + g;
                const unsigned int* Wsu = (const unsigned int*)Ws[s];
                bf[na][0] = Wsu[(k8 + tg)     * SW + cc];
                bf[na][1] = Wsu[(k8 + tg + 4) * SW + cc];
            }
            #pragma unroll
            for (int ma = 0; ma < 2; ma++)
                #pragma unroll
                for (int na = 0; na < 8; na++) {
                    asm volatile(
                        "mma.sync.aligned.m16n8k8.row.col.f32.tf32.tf32.f32 "
                        "{%0,%1,%2,%3}, {%4,%5,%6,%7}, {%8,%9}, {%0,%1,%2,%3};\n"
                        : "+f"(acc[ma][na][0]), "+f"(acc[ma][na][1]),
                          "+f"(acc[ma][na][2]), "+f"(acc[ma][na][3])
                        : "r"(af[ma][0]), "r"(af[ma][1]),
                          "r"(af[ma][2]), "r"(af[ma][3]),
                          "r"(bf[na][0]), "r"(bf[na][1]));
                }
        }
        __syncthreads();
    }

    #pragma unroll
    for (int ma = 0; ma < 2; ma++) {
        int r0g = block_row + wr * 32 + ma * 16 + g;
        int r1g = r0g + 8;
        float m0 = (r0g < N) ? mask[r0g] : 0.f;
        float m1 = (r1g < N) ? mask[r1g] : 0.f;
        if (MPOW == 2) { m0 *= m0; m1 *= m1; }
        #pragma unroll
        for (int na = 0; na < 8; na++) {
            int col = wc * 64 + na * 8 + 2 * tg;
            if (r0g < N) {
                __half2 h = __floats2half2_rn(acc[ma][na][0] * m0,
                                              acc[ma][na][1] * m0);
                *(__half2*)(C + (size_t)r0g * 128 + col) = h;
            }
            if (r1g < N) {
                __half2 h = __floats2half2_rn(acc[ma][na][2] * m1,
                                              acc[ma][na][3] * m1);
                *(__half2*)(C + (size_t)r1g * 128 + col) = h;
            }
        }
    }
}

// ---------------------------------------------------------------------------
// Gather v4: 2 nodes per warp, 16 lanes per node, 8 columns per lane.
// HFMA2 accumulation: 4 rotating half2 accumulator groups (8 terms per fp16
// chain) flushed once to fp32 -> per-k issue cost = LDS + LDG + 4 HFMA2.
// w staged as duplicated half2 at load time. pairs padded (+4) so the two
// node-halves hit different smem banks.
// ---------------------------------------------------------------------------
template <bool FUSE_LOGMAP>
__global__ __launch_bounds__(256)
void gather_kernel(const int*    __restrict__ adj,
                   const float*  __restrict__ wgt,
                   const float*  __restrict__ mask,
                   const __half* __restrict__ msg,
                   float* __restrict__ xout,
                   int N) {
    __shared__ int2 pairs[8][2][KK + 4];    // [warp][node-half][k], padded

    int tid   = threadIdx.x;
    int warp  = tid >> 5;
    int lane  = tid & 31;
    int half  = lane >> 4;              // which node within warp
    int hl    = lane & 15;              // lane within node (owns 8 cols)
    int node0 = blockIdx.x * 16 + warp * 2;
    int gnode = node0 + half;

    // stage both nodes' (adj, w-as-half2dup) rows: 64 pairs/warp, 2 per lane
    #pragma unroll
    for (int i = 0; i < 2; i++) {
        int idx = lane + i * 32;        // 0..63
        int h   = idx >> 5;
        int k   = idx & 31;
        int gn  = node0 + h;
        if (gn < N) {
            __half2 wh = __float2half2_rn(wgt[(size_t)gn * KK + k]);
            pairs[warp][h][k].x = adj[(size_t)gn * KK + k];
            pairs[warp][h][k].y = *(int*)&wh;
        }
    }
    __syncwarp();
    if (gnode >= N) return;

    const __half* mrow = msg + hl * 8;

    __half2 acch[4][4];
    #pragma unroll
    for (int g = 0; g < 4; g++)
        #pragma unroll
        for (int j = 0; j < 4; j++) acch[g][j] = __floats2half2_rn(0.f, 0.f);

    #pragma unroll
    for (int k = 0; k < KK; k++) {
        int2 p = pairs[warp][half][k];            // LDS.64 broadcast
        __half2 wh = *(__half2*)&p.y;
        uint4 raw = *(const uint4*)(mrow + (size_t)p.x * DD);
        int gr = k & 3;                            // rotating group
        acch[gr][0] = __hfma2(wh, *(__half2*)&raw.x, acch[gr][0]);
        acch[gr][1] = __hfma2(wh, *(__half2*)&raw.y, acch[gr][1]);
        acch[gr][2] = __hfma2(wh, *(__half2*)&raw.z, acch[gr][2]);
        acch[gr][3] = __hfma2(wh, *(__half2*)&raw.w, acch[gr][3]);
    }

    // flush fp16 groups to fp32
    float acc[8];
    #pragma unroll
    for (int i = 0; i < 8; i++) acc[i] = 0.f;
    #pragma unroll
    for (int g = 0; g < 4; g++)
        #pragma unroll
        for (int j = 0; j < 4; j++) {
            float2 f = __half22float2(acch[g][j]);
            acc[2 * j]     += f.x;
            acc[2 * j + 1] += f.y;
        }

    float mk = mask[gnode];
    #pragma unroll
    for (int i = 0; i < 8; i++) acc[i] *= mk;     // combined

    // exp-map at origin (norm over this node's 16 lanes x 8 cols)
    float s = 0.f;
    #pragma unroll
    for (int i = 0; i < 8; i++) s = fmaf(acc[i], acc[i], s);
    #pragma unroll
    for (int o = 8; o > 0; o >>= 1) s += __shfl_xor_sync(0xffffffffu, s, o);
    float n  = sqrtf(s);
    float nc = fminf(fmaxf(n, 1e-5f), 15.0f);
    float scale = tanhf(nc) / fmaxf(n, 1e-5f) * mk;   // expmap * mask

    float x[8];
    #pragma unroll
    for (int i = 0; i < 8; i++) x[i] = fmaxf(acc[i] * scale, 0.f) * mk;

    if (FUSE_LOGMAP) {
        float s2 = 0.f;
        #pragma unroll
        for (int i = 0; i < 8; i++) s2 = fmaf(x[i], x[i], s2);
        #pragma unroll
        for (int o = 8; o > 0; o >>= 1) s2 += __shfl_xor_sync(0xffffffffu, s2, o);
        float n2  = sqrtf(s2);
        float nc2 = fminf(fmaxf(n2, 1e-5f), 1.0f - 1e-5f);
        float ls  = atanhf(nc2) / fmaxf(n2, 1e-5f) * mk;
        #pragma unroll
        for (int i = 0; i < 8; i++) x[i] *= ls;
    }

    float* dst = xout + (size_t)gnode * DD + hl * 8;
    *(float4*)(dst)     = make_float4(x[0], x[1], x[2], x[3]);
    *(float4*)(dst + 4) = make_float4(x[4], x[5], x[6], x[7]);
}

// ---------------------------------------------------------------------------
extern "C" void kernel_launch(void* const* d_in, const int* in_sizes, int n_in,
                              void* d_out, int out_size) {
    const float* node_repr = (const float*)d_in[0];
    const int*   adj       = (const int*)  d_in[1];
    const float* weight    = (const float*)d_in[2];
    const float* mask      = (const float*)d_in[3];
    const float* msg_w     = (const float*)d_in[4];

    int N = in_sizes[0] / DD;
    float* out = (float*)d_out;

    float*  xbuf;
    __half* mbuf;
    cudaGetSymbolAddress((void**)&xbuf, g_x);
    cudaGetSymbolAddress((void**)&mbuf, g_msg);

    int gatherBlocks = (N + 15) / 16;       // 16 nodes per 256-thread block
    int gemmBlocks   = (N + 127) / 128;

    // ---- Layer 0 ----  ((x*m)@W*m = m^2*(x@W): mask^2 in epilogue)
    gemm_tc_kernel<2><<<gemmBlocks, 256>>>(node_repr, msg_w, mask, mbuf, N);
    gather_kernel<true><<<gatherBlocks, 256>>>(adj, weight, mask, mbuf, xbuf, N);

    // ---- Layer 1 ----  (xbuf already tangent-space * mask)
    gemm_tc_kernel<1><<<gemmBlocks, 256>>>(xbuf, msg_w + DD * DD, mask, mbuf, N);
    gather_kernel<false><<<gatherBlocks, 256>>>(adj, weight, mask, mbuf, out, N);
}

// round 10
// speedup vs baseline: 1.0827x; 1.0827x over previous
#include <cuda_runtime.h>
#include <cuda_fp16.h>
#include <cstdint>
#include <math.h>

#define DD 128
#define KK 32
#define NMAX 50000

// Scratch (allocation-free rule: __device__ globals)
__device__ __half  g_xh[NMAX * DD];       // layer-1 GEMM input (fp16)
__device__ __half  g_msg[NMAX * DD];      // messages (fp16)
__device__ __half2 g_wh[2 * 64 * DD];     // W pre-paired: [layer][k2][n] half2(W[2k2][n],W[2k2+1][n])

// ---------------------------------------------------------------------------
__device__ __forceinline__ void cp16(void* dst_smem, const void* src, bool pred) {
    unsigned sdst = (unsigned)__cvta_generic_to_shared(dst_smem);
    int sz = pred ? 16 : 0;
    asm volatile("cp.async.cg.shared.global [%0], [%1], 16, %2;\n"
                 :: "r"(sdst), "l"(src), "r"(sz));
}

// ---------------------------------------------------------------------------
// Prep: pair W rows (k, k+1) into half2, k2-major layout for direct cp.async.
// ---------------------------------------------------------------------------
__global__ void prep_w_kernel(const float* __restrict__ W, __half2* __restrict__ out) {
    int gid = blockIdx.x * blockDim.x + threadIdx.x;   // 0..16383
    int l   = gid >> 13;
    int rem = gid & 8191;
    int k2  = rem >> 7;
    int n   = rem & 127;
    float a = W[l * 16384 + 2 * k2 * 128 + n];
    float b = W[l * 16384 + (2 * k2 + 1) * 128 + n];
    out[gid] = __floats2half2_rn(a, b);
}

// ---------------------------------------------------------------------------
// fp16 tensor-core GEMM: C[N,128] = A @ W, epilogue * mask^MPOW, fp16 out.
// mma.sync.m16n8k16.f32.f16.f16.f32, 2-stage cp.async pipeline, BK=16.
// 8 warps as 4(row) x 2(col); warp tile 32x64 = 2x8 atoms.
// As2[row][k2] stride 12 half2-words; Ws2[k2][col] stride 136. Conflict-free.
// ---------------------------------------------------------------------------
#define SAH 12
#define SWH 136

template <typename AT, int MPOW>
__global__ __launch_bounds__(256, 2)
void gemm_tc_kernel(const AT* __restrict__ A,
                    const __half2* __restrict__ Wh,   // [64][128] half2
                    const float* __restrict__ mask,
                    __half* __restrict__ C,
                    int N) {
    __shared__ __half2 As2[2][128 * SAH];
    __shared__ __half2 Ws2[2][8 * SWH];

    int tid  = threadIdx.x;
    int lane = tid & 31;
    int warp = tid >> 5;
    int wr   = warp >> 1;
    int wc   = warp & 1;
    int g    = lane >> 2;
    int tg   = lane & 3;

    int block_row = blockIdx.x * 128;

    float acc[2][8][4];
    #pragma unroll
    for (int ma = 0; ma < 2; ma++)
        #pragma unroll
        for (int na = 0; na < 8; na++)
            #pragma unroll
            for (int i = 0; i < 4; i++) acc[ma][na][i] = 0.f;

    int arow = tid >> 1;            // 0..127
    int ahk  = tid & 1;             // which 8-elem half of the 16-k slice
    int grow = block_row + arow;
    int wk2  = tid >> 5;            // 0..7
    int wc4  = tid & 31;            // 0..31

    #define LOAD_TILES(s, k0)                                                   \
    {                                                                           \
        if (sizeof(AT) == 4) {                                                  \
            float4 v0 = make_float4(0.f,0.f,0.f,0.f), v1 = v0;                  \
            if (grow < N) {                                                     \
                const float* Ap = (const float*)A + (size_t)grow * 128 + (k0) + ahk * 8; \
                v0 = *(const float4*)(Ap);                                      \
                v1 = *(const float4*)(Ap + 4);                                  \
            }                                                                   \
            __half2 h0 = __floats2half2_rn(v0.x, v0.y);                         \
            __half2 h1 = __floats2half2_rn(v0.z, v0.w);                         \
            __half2 h2 = __floats2half2_rn(v1.x, v1.y);                         \
            __half2 h3 = __floats2half2_rn(v1.z, v1.w);                         \
            uint4 u = make_uint4(*(unsigned*)&h0, *(unsigned*)&h1,              \
                                 *(unsigned*)&h2, *(unsigned*)&h3);             \
            *(uint4*)&As2[s][arow * SAH + ahk * 4] = u;                         \
        } else {                                                                \
            cp16(&As2[s][arow * SAH + ahk * 4],                                 \
                 (const __half*)A + (size_t)grow * 128 + (k0) + ahk * 8,        \
                 grow < N);                                                     \
        }                                                                       \
        cp16(&Ws2[s][wk2 * SWH + wc4 * 4],                                      \
             Wh + ((k0) / 2 + wk2) * 128 + wc4 * 4, true);                      \
        asm volatile("cp.async.commit_group;\n");                               \
    }

    LOAD_TILES(0, 0);

    #pragma unroll
    for (int it = 0; it < 8; it++) {
        int s = it & 1;
        if (it < 7) LOAD_TILES(s ^ 1, (it + 1) * 16);
        if (it < 7) asm volatile("cp.async.wait_group 1;\n");
        else        asm volatile("cp.async.wait_group 0;\n");
        __syncthreads();

        unsigned af[2][4];
        #pragma unroll
        for (int ma = 0; ma < 2; ma++) {
            int r = wr * 32 + ma * 16;
            const unsigned* Asu = (const unsigned*)As2[s];
            af[ma][0] = Asu[(r + g)     * SAH + tg];
            af[ma][1] = Asu[(r + g + 8) * SAH + tg];
            af[ma][2] = Asu[(r + g)     * SAH + tg + 4];
            af[ma][3] = Asu[(r + g + 8) * SAH + tg + 4];
        }
        unsigned bf[8][2];
        #pragma unroll
        for (int na = 0; na < 8; na++) {
            int cc = wc * 64 + na * 8 + g;
            const unsigned* Wsu = (const unsigned*)Ws2[s];
            bf[na][0] = Wsu[tg       * SWH + cc];
            bf[na][1] = Wsu[(tg + 4) * SWH + cc];
        }
        #pragma unroll
        for (int ma = 0; ma < 2; ma++)
            #pragma unroll
            for (int na = 0; na < 8; na++) {
                asm volatile(
                    "mma.sync.aligned.m16n8k16.row.col.f32.f16.f16.f32 "
                    "{%0,%1,%2,%3}, {%4,%5,%6,%7}, {%8,%9}, {%0,%1,%2,%3};\n"
                    : "+f"(acc[ma][na][0]), "+f"(acc[ma][na][1]),
                      "+f"(acc[ma][na][2]), "+f"(acc[ma][na][3])
                    : "r"(af[ma][0]), "r"(af[ma][1]),
                      "r"(af[ma][2]), "r"(af[ma][3]),
                      "r"(bf[na][0]), "r"(bf[na][1]));
            }
        __syncthreads();
    }

    // Epilogue: * mask^MPOW, fp16 stores (C layout: rows g/g+8, cols 2tg,2tg+1)
    #pragma unroll
    for (int ma = 0; ma < 2; ma++) {
        int r0g = block_row + wr * 32 + ma * 16 + g;
        int r1g = r0g + 8;
        float m0 = (r0g < N) ? mask[r0g] : 0.f;
        float m1 = (r1g < N) ? mask[r1g] : 0.f;
        if (MPOW == 2) { m0 *= m0; m1 *= m1; }
        #pragma unroll
        for (int na = 0; na < 8; na++) {
            int col = wc * 64 + na * 8 + 2 * tg;
            if (r0g < N) {
                __half2 h = __floats2half2_rn(acc[ma][na][0] * m0,
                                              acc[ma][na][1] * m0);
                *(__half2*)(C + (size_t)r0g * 128 + col) = h;
            }
            if (r1g < N) {
                __half2 h = __floats2half2_rn(acc[ma][na][2] * m1,
                                              acc[ma][na][3] * m1);
                *(__half2*)(C + (size_t)r1g * 128 + col) = h;
            }
        }
    }
}

// ---------------------------------------------------------------------------
// Gather (R7 form — empirical best): 2 nodes/warp, 16 lanes/node, 8 cols/lane,
// LDG.128 per lane per k. FUSE_LOGMAP=true also applies next-layer log-map and
// writes fp16; otherwise writes fp32 (final output).
// ---------------------------------------------------------------------------
template <bool FUSE_LOGMAP>
__global__ __launch_bounds__(256)
void gather_kernel(const int*    __restrict__ adj,
                   const float*  __restrict__ wgt,
                   const float*  __restrict__ mask,
                   const __half* __restrict__ msg,
                   void* __restrict__ xout,
                   int N) {
    __shared__ int2 pairs[8][2][KK];

    int tid   = threadIdx.x;
    int warp  = tid >> 5;
    int lane  = tid & 31;
    int half  = lane >> 4;
    int hl    = lane & 15;
    int node0 = blockIdx.x * 16 + warp * 2;
    int gnode = node0 + half;

    #pragma unroll
    for (int i = 0; i < 2; i++) {
        int idx = lane + i * 32;
        int h   = idx >> 5;
        int k   = idx & 31;
        int gn  = node0 + h;
        if (gn < N) {
            pairs[warp][h][k].x = adj[(size_t)gn * KK + k];
            pairs[warp][h][k].y = __float_as_int(wgt[(size_t)gn * KK + k]);
        }
    }
    __syncwarp();
    if (gnode >= N) return;

    float acc[8];
    #pragma unroll
    for (int i = 0; i < 8; i++) acc[i] = 0.f;

    #pragma unroll
    for (int k = 0; k < KK; k++) {
        int2 p = pairs[warp][half][k];
        float wk = __int_as_float(p.y);
        uint4 raw = *(const uint4*)(msg + (size_t)p.x * DD + hl * 8);
        float2 f0 = __half22float2(*(__half2*)&raw.x);
        float2 f1 = __half22float2(*(__half2*)&raw.y);
        float2 f2 = __half22float2(*(__half2*)&raw.z);
        float2 f3 = __half22float2(*(__half2*)&raw.w);
        acc[0] = fmaf(wk, f0.x, acc[0]);
        acc[1] = fmaf(wk, f0.y, acc[1]);
        acc[2] = fmaf(wk, f1.x, acc[2]);
        acc[3] = fmaf(wk, f1.y, acc[3]);
        acc[4] = fmaf(wk, f2.x, acc[4]);
        acc[5] = fmaf(wk, f2.y, acc[5]);
        acc[6] = fmaf(wk, f3.x, acc[6]);
        acc[7] = fmaf(wk, f3.y, acc[7]);
    }

    float mk = mask[gnode];
    #pragma unroll
    for (int i = 0; i < 8; i++) acc[i] *= mk;

    float s = 0.f;
    #pragma unroll
    for (int i = 0; i < 8; i++) s = fmaf(acc[i], acc[i], s);
    #pragma unroll
    for (int o = 8; o > 0; o >>= 1) s += __shfl_xor_sync(0xffffffffu, s, o);
    float n  = sqrtf(s);
    float nc = fminf(fmaxf(n, 1e-5f), 15.0f);
    float scale = tanhf(nc) / fmaxf(n, 1e-5f) * mk;

    float x[8];
    #pragma unroll
    for (int i = 0; i < 8; i++) x[i] = fmaxf(acc[i] * scale, 0.f) * mk;

    if (FUSE_LOGMAP) {
        float s2 = 0.f;
        #pragma unroll
        for (int i = 0; i < 8; i++) s2 = fmaf(x[i], x[i], s2);
        #pragma unroll
        for (int o = 8; o > 0; o >>= 1) s2 += __shfl_xor_sync(0xffffffffu, s2, o);
        float n2  = sqrtf(s2);
        float nc2 = fminf(fmaxf(n2, 1e-5f), 1.0f - 1e-5f);
        float ls  = atanhf(nc2) / fmaxf(n2, 1e-5f) * mk;
        #pragma unroll
        for (int i = 0; i < 8; i++) x[i] *= ls;

        __half2 h0 = __floats2half2_rn(x[0], x[1]);
        __half2 h1 = __floats2half2_rn(x[2], x[3]);
        __half2 h2 = __floats2half2_rn(x[4], x[5]);
        __half2 h3 = __floats2half2_rn(x[6], x[7]);
        uint4 u = make_uint4(*(unsigned*)&h0, *(unsigned*)&h1,
                             *(unsigned*)&h2, *(unsigned*)&h3);
        *(uint4*)((__half*)xout + (size_t)gnode * DD + hl * 8) = u;
    } else {
        float* dst = (float*)xout + (size_t)gnode * DD + hl * 8;
        *(float4*)(dst)     = make_float4(x[0], x[1], x[2], x[3]);
        *(float4*)(dst + 4) = make_float4(x[4], x[5], x[6], x[7]);
    }
}

// ---------------------------------------------------------------------------
extern "C" void kernel_launch(void* const* d_in, const int* in_sizes, int n_in,
                              void* d_out, int out_size) {
    const float* node_repr = (const float*)d_in[0];
    const int*   adj       = (const int*)  d_in[1];
    const float* weight    = (const float*)d_in[2];
    const float* mask      = (const float*)d_in[3];
    const float* msg_w     = (const float*)d_in[4];

    int N = in_sizes[0] / DD;

    __half*  xbuf;
    __half*  mbuf;
    __half2* whbuf;
    cudaGetSymbolAddress((void**)&xbuf, g_xh);
    cudaGetSymbolAddress((void**)&mbuf, g_msg);
    cudaGetSymbolAddress((void**)&whbuf, g_wh);

    int gatherBlocks = (N + 15) / 16;
    int gemmBlocks   = (N + 127) / 128;

    // Pre-pair both layers' W into half2 (k2-major)
    prep_w_kernel<<<64, 256>>>(msg_w, whbuf);

    // ---- Layer 0 ----  ((x*m)@W*m = m^2*(x@W): mask^2 in epilogue)
    gemm_tc_kernel<float, 2><<<gemmBlocks, 256>>>(node_repr, whbuf, mask, mbuf, N);
    gather_kernel<true><<<gatherBlocks, 256>>>(adj, weight, mask, mbuf, xbuf, N);

    // ---- Layer 1 ----  (xbuf fp16, tangent-space * mask)
    gemm_tc_kernel<__half, 1><<<gemmBlocks, 256>>>(xbuf, whbuf + 64 * DD, mask, mbuf, N);
    gather_kernel<false><<<gatherBlocks, 256>>>(adj, weight, mask, mbuf, d_out, N);
}

// round 11
// speedup vs baseline: 1.1274x; 1.0413x over previous
#include <cuda_runtime.h>
#include <cuda_fp16.h>
#include <cstdint>
#include <math.h>

#define DD 128
#define KK 32
#define NMAX 50000

// Scratch (allocation-free rule: __device__ globals)
__device__ __half  g_xh[NMAX * DD];       // layer-1 GEMM input (fp16)
__device__ __half  g_msg[NMAX * DD];      // messages (fp16)
__device__ __half2 g_wh[2 * 64 * DD];     // W pre-paired: [layer][k2][n]

// ---------------------------------------------------------------------------
__device__ __forceinline__ void cp16(void* dst_smem, const void* src, bool pred) {
    unsigned sdst = (unsigned)__cvta_generic_to_shared(dst_smem);
    int sz = pred ? 16 : 0;
    asm volatile("cp.async.cg.shared.global [%0], [%1], 16, %2;\n"
                 :: "r"(sdst), "l"(src), "r"(sz));
}

// ---------------------------------------------------------------------------
// Prep: pair W rows (k, k+1) into half2, k2-major layout for direct cp.async.
// ---------------------------------------------------------------------------
__global__ void prep_w_kernel(const float* __restrict__ W, __half2* __restrict__ out) {
    int gid = blockIdx.x * blockDim.x + threadIdx.x;   // 0..16383
    int l   = gid >> 13;
    int rem = gid & 8191;
    int k2  = rem >> 7;
    int n   = rem & 127;
    float a = W[l * 16384 + 2 * k2 * 128 + n];
    float b = W[l * 16384 + (2 * k2 + 1) * 128 + n];
    out[gid] = __floats2half2_rn(a, b);
}

// ---------------------------------------------------------------------------
// Persistent fp16 GEMM: C[N,128] = A @ W, epilogue * mask^MPOW, fp16 out.
// W (full 128x128) resident in smem; per 128-row tile: one A stage (double-
// buffered cp.async) + 2 syncs + 128 back-to-back m16n8k16 MMAs per warp.
// Grid = 2 blocks/SM, tiles strided by gridDim.
// Smem: Ws2[64][136] half2 (34816B) + As2[2][128][68] half2 (69632B).
// ---------------------------------------------------------------------------
#define SAH 68
#define SWH 136
#define GEMM_SMEM (64 * SWH * 4 + 2 * 128 * SAH * 4)

template <typename AT, int MPOW>
__global__ __launch_bounds__(256, 2)
void gemm_tc_kernel(const AT* __restrict__ A,
                    const __half2* __restrict__ Wh,   // [64][128] half2
                    const float* __restrict__ mask,
                    __half* __restrict__ C,
                    int N, int NT) {
    extern __shared__ __half2 smem[];
    __half2* Ws2 = smem;                 // 64*SWH
    __half2* As2 = smem + 64 * SWH;      // 2 stages of 128*SAH

    int tid  = threadIdx.x;
    int lane = tid & 31;
    int warp = tid >> 5;
    int wr   = warp >> 1;
    int wc   = warp & 1;
    int g    = lane >> 2;
    int tg   = lane & 3;

    // ---- load full W: 2048 cp16, 8 per thread ----
    #pragma unroll
    for (int i = 0; i < 8; i++) {
        int idx = tid + i * 256;         // 0..2047
        int k2  = idx >> 5;              // 0..63
        int c4  = idx & 31;              // 0..31
        cp16(&Ws2[k2 * SWH + c4 * 4], Wh + k2 * 128 + c4 * 4, true);
    }

    // ---- A tile stager: 2048 cp16 (fp16) or LDG+CVT+STS (fp32) ----
    #define STAGE_A(s, tile)                                                    \
    {                                                                           \
        int base_row = (tile) * 128;                                            \
        _Pragma("unroll")                                                       \
        for (int i = 0; i < 8; i++) {                                           \
            int idx  = tid + i * 256;                                           \
            int row  = idx >> 4;                                                \
            int c4   = idx & 15;                                                \
            int grow = base_row + row;                                          \
            if (sizeof(AT) == 4) {                                              \
                float4 v0 = make_float4(0.f,0.f,0.f,0.f), v1 = v0;              \
                if (grow < N) {                                                 \
                    const float* Ap = (const float*)A + (size_t)grow * 128 + c4 * 8; \
                    v0 = *(const float4*)(Ap);                                  \
                    v1 = *(const float4*)(Ap + 4);                              \
                }                                                               \
                __half2 h0 = __floats2half2_rn(v0.x, v0.y);                     \
                __half2 h1 = __floats2half2_rn(v0.z, v0.w);                     \
                __half2 h2 = __floats2half2_rn(v1.x, v1.y);                     \
                __half2 h3 = __floats2half2_rn(v1.z, v1.w);                     \
                uint4 u = make_uint4(*(unsigned*)&h0, *(unsigned*)&h1,          \
                                     *(unsigned*)&h2, *(unsigned*)&h3);         \
                *(uint4*)&As2[(s) * 128 * SAH + row * SAH + c4 * 4] = u;        \
            } else {                                                            \
                cp16(&As2[(s) * 128 * SAH + row * SAH + c4 * 4],                \
                     (const __half*)A + (size_t)grow * 128 + c4 * 8,            \
                     grow < N);                                                 \
            }                                                                   \
        }                                                                       \
        asm volatile("cp.async.commit_group;\n");                               \
    }

    int t0 = blockIdx.x;
    STAGE_A(0, t0);

    for (int t = t0, it = 0; t < NT; t += gridDim.x, it++) {
        int s = it & 1;
        bool more = (t + (int)gridDim.x) < NT;
        if (more) STAGE_A(s ^ 1, t + gridDim.x);
        if (more) asm volatile("cp.async.wait_group 1;\n");
        else      asm volatile("cp.async.wait_group 0;\n");
        __syncthreads();

        float acc[2][8][4];
        #pragma unroll
        for (int ma = 0; ma < 2; ma++)
            #pragma unroll
            for (int na = 0; na < 8; na++)
                #pragma unroll
                for (int i = 0; i < 4; i++) acc[ma][na][i] = 0.f;

        const unsigned* Asu = (const unsigned*)(As2 + s * 128 * SAH);
        const unsigned* Wsu = (const unsigned*)Ws2;

        #pragma unroll
        for (int ks = 0; ks < 8; ks++) {
            int k2 = ks * 8;
            unsigned af[2][4];
            #pragma unroll
            for (int ma = 0; ma < 2; ma++) {
                int r = wr * 32 + ma * 16;
                af[ma][0] = Asu[(r + g)     * SAH + k2 + tg];
                af[ma][1] = Asu[(r + g + 8) * SAH + k2 + tg];
                af[ma][2] = Asu[(r + g)     * SAH + k2 + tg + 4];
                af[ma][3] = Asu[(r + g + 8) * SAH + k2 + tg + 4];
            }
            unsigned bf[8][2];
            #pragma unroll
            for (int na = 0; na < 8; na++) {
                int cc = wc * 64 + na * 8 + g;
                bf[na][0] = Wsu[(k2 + tg)     * SWH + cc];
                bf[na][1] = Wsu[(k2 + tg + 4) * SWH + cc];
            }
            #pragma unroll
            for (int ma = 0; ma < 2; ma++)
                #pragma unroll
                for (int na = 0; na < 8; na++) {
                    asm volatile(
                        "mma.sync.aligned.m16n8k16.row.col.f32.f16.f16.f32 "
                        "{%0,%1,%2,%3}, {%4,%5,%6,%7}, {%8,%9}, {%0,%1,%2,%3};\n"
                        : "+f"(acc[ma][na][0]), "+f"(acc[ma][na][1]),
                          "+f"(acc[ma][na][2]), "+f"(acc[ma][na][3])
                        : "r"(af[ma][0]), "r"(af[ma][1]),
                          "r"(af[ma][2]), "r"(af[ma][3]),
                          "r"(bf[na][0]), "r"(bf[na][1]));
                }
        }

        // Epilogue for this tile
        int block_row = t * 128;
        #pragma unroll
        for (int ma = 0; ma < 2; ma++) {
            int r0g = block_row + wr * 32 + ma * 16 + g;
            int r1g = r0g + 8;
            float m0 = (r0g < N) ? mask[r0g] : 0.f;
            float m1 = (r1g < N) ? mask[r1g] : 0.f;
            if (MPOW == 2) { m0 *= m0; m1 *= m1; }
            #pragma unroll
            for (int na = 0; na < 8; na++) {
                int col = wc * 64 + na * 8 + 2 * tg;
                if (r0g < N) {
                    __half2 h = __floats2half2_rn(acc[ma][na][0] * m0,
                                                  acc[ma][na][1] * m0);
                    *(__half2*)(C + (size_t)r0g * 128 + col) = h;
                }
                if (r1g < N) {
                    __half2 h = __floats2half2_rn(acc[ma][na][2] * m1,
                                                  acc[ma][na][3] * m1);
                    *(__half2*)(C + (size_t)r1g * 128 + col) = h;
                }
            }
        }
        __syncthreads();   // protect A buffer s before it is re-staged
    }
}

// ---------------------------------------------------------------------------
// Gather (R7 form — empirical best): 2 nodes/warp, 16 lanes/node, 8 cols/lane.
// FUSE_LOGMAP=true applies next-layer log-map and writes fp16; else fp32 out.
// ---------------------------------------------------------------------------
template <bool FUSE_LOGMAP>
__global__ __launch_bounds__(256)
void gather_kernel(const int*    __restrict__ adj,
                   const float*  __restrict__ wgt,
                   const float*  __restrict__ mask,
                   const __half* __restrict__ msg,
                   void* __restrict__ xout,
                   int N) {
    __shared__ int2 pairs[8][2][KK];

    int tid   = threadIdx.x;
    int warp  = tid >> 5;
    int lane  = tid & 31;
    int half  = lane >> 4;
    int hl    = lane & 15;
    int node0 = blockIdx.x * 16 + warp * 2;
    int gnode = node0 + half;

    #pragma unroll
    for (int i = 0; i < 2; i++) {
        int idx = lane + i * 32;
        int h   = idx >> 5;
        int k   = idx & 31;
        int gn  = node0 + h;
        if (gn < N) {
            pairs[warp][h][k].x = adj[(size_t)gn * KK + k];
            pairs[warp][h][k].y = __float_as_int(wgt[(size_t)gn * KK + k]);
        }
    }
    __syncwarp();
    if (gnode >= N) return;

    float acc[8];
    #pragma unroll
    for (int i = 0; i < 8; i++) acc[i] = 0.f;

    #pragma unroll
    for (int k = 0; k < KK; k++) {
        int2 p = pairs[warp][half][k];
        float wk = __int_as_float(p.y);
        uint4 raw = *(const uint4*)(msg + (size_t)p.x * DD + hl * 8);
        float2 f0 = __half22float2(*(__half2*)&raw.x);
        float2 f1 = __half22float2(*(__half2*)&raw.y);
        float2 f2 = __half22float2(*(__half2*)&raw.z);
        float2 f3 = __half22float2(*(__half2*)&raw.w);
        acc[0] = fmaf(wk, f0.x, acc[0]);
        acc[1] = fmaf(wk, f0.y, acc[1]);
        acc[2] = fmaf(wk, f1.x, acc[2]);
        acc[3] = fmaf(wk, f1.y, acc[3]);
        acc[4] = fmaf(wk, f2.x, acc[4]);
        acc[5] = fmaf(wk, f2.y, acc[5]);
        acc[6] = fmaf(wk, f3.x, acc[6]);
        acc[7] = fmaf(wk, f3.y, acc[7]);
    }

    float mk = mask[gnode];
    #pragma unroll
    for (int i = 0; i < 8; i++) acc[i] *= mk;

    float s = 0.f;
    #pragma unroll
    for (int i = 0; i < 8; i++) s = fmaf(acc[i], acc[i], s);
    #pragma unroll
    for (int o = 8; o > 0; o >>= 1) s += __shfl_xor_sync(0xffffffffu, s, o);
    float n  = sqrtf(s);
    float nc = fminf(fmaxf(n, 1e-5f), 15.0f);
    float scale = tanhf(nc) / fmaxf(n, 1e-5f) * mk;

    float x[8];
    #pragma unroll
    for (int i = 0; i < 8; i++) x[i] = fmaxf(acc[i] * scale, 0.f) * mk;

    if (FUSE_LOGMAP) {
        float s2 = 0.f;
        #pragma unroll
        for (int i = 0; i < 8; i++) s2 = fmaf(x[i], x[i], s2);
        #pragma unroll
        for (int o = 8; o > 0; o >>= 1) s2 += __shfl_xor_sync(0xffffffffu, s2, o);
        float n2  = sqrtf(s2);
        float nc2 = fminf(fmaxf(n2, 1e-5f), 1.0f - 1e-5f);
        float ls  = atanhf(nc2) / fmaxf(n2, 1e-5f) * mk;
        #pragma unroll
        for (int i = 0; i < 8; i++) x[i] *= ls;

        __half2 h0 = __floats2half2_rn(x[0], x[1]);
        __half2 h1 = __floats2half2_rn(x[2], x[3]);
        __half2 h2 = __floats2half2_rn(x[4], x[5]);
        __half2 h3 = __floats2half2_rn(x[6], x[7]);
        uint4 u = make_uint4(*(unsigned*)&h0, *(unsigned*)&h1,
                             *(unsigned*)&h2, *(unsigned*)&h3);
        *(uint4*)((__half*)xout + (size_t)gnode * DD + hl * 8) = u;
    } else {
        float* dst = (float*)xout + (size_t)gnode * DD + hl * 8;
        *(float4*)(dst)     = make_float4(x[0], x[1], x[2], x[3]);
        *(float4*)(dst + 4) = make_float4(x[4], x[5], x[6], x[7]);
    }
}

// ---------------------------------------------------------------------------
extern "C" void kernel_launch(void* const* d_in, const int* in_sizes, int n_in,
                              void* d_out, int out_size) {
    const float* node_repr = (const float*)d_in[0];
    const int*   adj       = (const int*)  d_in[1];
    const float* weight    = (const float*)d_in[2];
    const float* mask      = (const float*)d_in[3];
    const float* msg_w     = (const float*)d_in[4];

    int N  = in_sizes[0] / DD;
    int NT = (N + 127) / 128;

    __half*  xbuf;
    __half*  mbuf;
    __half2* whbuf;
    cudaGetSymbolAddress((void**)&xbuf, g_xh);
    cudaGetSymbolAddress((void**)&mbuf, g_msg);
    cudaGetSymbolAddress((void**)&whbuf, g_wh);

    static bool attr_done = false;
    if (!attr_done) {
        cudaFuncSetAttribute(gemm_tc_kernel<float, 2>,
                             cudaFuncAttributeMaxDynamicSharedMemorySize, GEMM_SMEM);
        cudaFuncSetAttribute(gemm_tc_kernel<__half, 1>,
                             cudaFuncAttributeMaxDynamicSharedMemorySize, GEMM_SMEM);
        attr_done = true;
    }

    int gatherBlocks = (N + 15) / 16;
    int gemmGrid     = NT < 296 ? NT : 296;

    // Pre-pair both layers' W into half2 (k2-major)
    prep_w_kernel<<<64, 256>>>(msg_w, whbuf);

    // ---- Layer 0 ----  ((x*m)@W*m = m^2*(x@W): mask^2 in epilogue)
    gemm_tc_kernel<float, 2><<<gemmGrid, 256, GEMM_SMEM>>>(node_repr, whbuf, mask, mbuf, N, NT);
    gather_kernel<true><<<gatherBlocks, 256>>>(adj, weight, mask, mbuf, xbuf, N);

    // ---- Layer 1 ----  (xbuf fp16, tangent-space * mask)
    gemm_tc_kernel<__half, 1><<<gemmGrid, 256, GEMM_SMEM>>>(xbuf, whbuf + 64 * DD, mask, mbuf, N, NT);
    gather_kernel<false><<<gatherBlocks, 256>>>(adj, weight, mask, mbuf, d_out, N);
}

// round 14
// speedup vs baseline: 1.1306x; 1.0028x over previous
#include <cuda_runtime.h>
#include <cuda_fp16.h>
#include <cstdint>
#include <math.h>

#define DD 128
#define KK 32
#define NMAX 50000

// Scratch (allocation-free rule: __device__ globals)
__device__ __half  g_xh[NMAX * DD];       // layer-1 GEMM input (fp16)
__device__ __half  g_msg[NMAX * DD];      // messages (fp16)
__device__ __half2 g_wh[2 * 64 * DD];     // W pre-paired: [layer][k2][n]

// ---------------------------------------------------------------------------
__device__ __forceinline__ void cp16(void* dst_smem, const void* src, bool pred) {
    unsigned sdst = (unsigned)__cvta_generic_to_shared(dst_smem);
    int sz = pred ? 16 : 0;
    asm volatile("cp.async.cg.shared.global [%0], [%1], 16, %2;\n"
                 :: "r"(sdst), "l"(src), "r"(sz));
}

// ---------------------------------------------------------------------------
// Prep: pair W rows (k, k+1) into half2, k2-major layout for direct cp.async.
// ---------------------------------------------------------------------------
__global__ void prep_w_kernel(const float* __restrict__ W, __half2* __restrict__ out) {
    int gid = blockIdx.x * blockDim.x + threadIdx.x;   // 0..16383
    int l   = gid >> 13;
    int rem = gid & 8191;
    int k2  = rem >> 7;
    int n   = rem & 127;
    float a = W[l * 16384 + 2 * k2 * 128 + n];
    float b = W[l * 16384 + (2 * k2 + 1) * 128 + n];
    out[gid] = __floats2half2_rn(a, b);
}

// ---------------------------------------------------------------------------
// One-shot fp16 GEMM: one 128-row tile per block, single wave, single sync.
// Stage whole W (cp.async) + whole-K A tile, wait, 128 m16n8k16 MMAs/warp,
// epilogue * mask^MPOW, fp16 out.
// Smem: Ws2[64][136] half2 (34816B) + As2[128][68] half2 (34816B) = 68KB.
// ---------------------------------------------------------------------------
#define SAH 68
#define SWH 136
#define GEMM_SMEM (64 * SWH * 4 + 128 * SAH * 4)

template <typename AT, int MPOW>
__global__ __launch_bounds__(256, 2)
void gemm_tc_kernel(const AT* __restrict__ A,
                    const __half2* __restrict__ Wh,   // [64][128] half2
                    const float* __restrict__ mask,
                    __half* __restrict__ C,
                    int N) {
    extern __shared__ __half2 smem[];
    __half2* Ws2 = smem;                 // 64*SWH
    __half2* As2 = smem + 64 * SWH;      // 128*SAH

    int tid  = threadIdx.x;
    int lane = tid & 31;
    int warp = tid >> 5;
    int wr   = warp >> 1;
    int wc   = warp & 1;
    int g    = lane >> 2;
    int tg   = lane & 3;

    int block_row = blockIdx.x * 128;

    // ---- stage full W: 2048 cp16, 8 per thread ----
    #pragma unroll
    for (int i = 0; i < 8; i++) {
        int idx = tid + i * 256;         // 0..2047
        int k2  = idx >> 5;              // 0..63
        int c4  = idx & 31;              // 0..31
        cp16(&Ws2[k2 * SWH + c4 * 4], Wh + k2 * 128 + c4 * 4, true);
    }

    // ---- stage whole-K A tile ----
    if (sizeof(AT) == 2) {
        // fp16 A: 2048 cp16, 8 per thread
        #pragma unroll
        for (int i = 0; i < 8; i++) {
            int idx  = tid + i * 256;
            int row  = idx >> 4;         // 0..127
            int c4   = idx & 15;         // 0..15
            int grow = block_row + row;
            cp16(&As2[row * SAH + c4 * 4],
                 (const __half*)A + (size_t)grow * 128 + c4 * 8, grow < N);
        }
        asm volatile("cp.async.commit_group;\n");
        asm volatile("cp.async.wait_group 0;\n");
    } else {
        asm volatile("cp.async.commit_group;\n");
        // fp32 A: LDG.128 + cvt + STS.128 (overlaps with W cp.async in flight)
        #pragma unroll
        for (int i = 0; i < 8; i++) {
            int idx  = tid + i * 256;
            int row  = idx >> 4;
            int c4   = idx & 15;
            int grow = block_row + row;
            float4 v0 = make_float4(0.f, 0.f, 0.f, 0.f), v1 = v0;
            if (grow < N) {
                const float* Ap = (const float*)A + (size_t)grow * 128 + c4 * 8;
                v0 = *(const float4*)(Ap);
                v1 = *(const float4*)(Ap + 4);
            }
            __half2 h0 = __floats2half2_rn(v0.x, v0.y);
            __half2 h1 = __floats2half2_rn(v0.z, v0.w);
            __half2 h2 = __floats2half2_rn(v1.x, v1.y);
            __half2 h3 = __floats2half2_rn(v1.z, v1.w);
            uint4 u = make_uint4(*(unsigned*)&h0, *(unsigned*)&h1,
                                 *(unsigned*)&h2, *(unsigned*)&h3);
            *(uint4*)&As2[row * SAH + c4 * 4] = u;
        }
        asm volatile("cp.async.wait_group 0;\n");
    }
    __syncthreads();   // the ONLY block-wide barrier

    float acc[2][8][4];
    #pragma unroll
    for (int ma = 0; ma < 2; ma++)
        #pragma unroll
        for (int na = 0; na < 8; na++)
            #pragma unroll
            for (int i = 0; i < 4; i++) acc[ma][na][i] = 0.f;

    const unsigned* Asu = (const unsigned*)As2;
    const unsigned* Wsu = (const unsigned*)Ws2;

    #pragma unroll
    for (int ks = 0; ks < 8; ks++) {
        int k2 = ks * 8;
        unsigned af[2][4];
        #pragma unroll
        for (int ma = 0; ma < 2; ma++) {
            int r = wr * 32 + ma * 16;
            af[ma][0] = Asu[(r + g)     * SAH + k2 + tg];
            af[ma][1] = Asu[(r + g + 8) * SAH + k2 + tg];
            af[ma][2] = Asu[(r + g)     * SAH + k2 + tg + 4];
            af[ma][3] = Asu[(r + g + 8) * SAH + k2 + tg + 4];
        }
        unsigned bf[8][2];
        #pragma unroll
        for (int na = 0; na < 8; na++) {
            int cc = wc * 64 + na * 8 + g;
            bf[na][0] = Wsu[(k2 + tg)     * SWH + cc];
            bf[na][1] = Wsu[(k2 + tg + 4) * SWH + cc];
        }
        #pragma unroll
        for (int ma = 0; ma < 2; ma++)
            #pragma unroll
            for (int na = 0; na < 8; na++) {
                asm volatile(
                    "mma.sync.aligned.m16n8k16.row.col.f32.f16.f16.f32 "
                    "{%0,%1,%2,%3}, {%4,%5,%6,%7}, {%8,%9}, {%0,%1,%2,%3};\n"
                    : "+f"(acc[ma][na][0]), "+f"(acc[ma][na][1]),
                      "+f"(acc[ma][na][2]), "+f"(acc[ma][na][3])
                    : "r"(af[ma][0]), "r"(af[ma][1]),
                      "r"(af[ma][2]), "r"(af[ma][3]),
                      "r"(bf[na][0]), "r"(bf[na][1]));
            }
    }

    // Epilogue: * mask^MPOW, fp16 stores
    #pragma unroll
    for (int ma = 0; ma < 2; ma++) {
        int r0g = block_row + wr * 32 + ma * 16 + g;
        int r1g = r0g + 8;
        float m0 = (r0g < N) ? mask[r0g] : 0.f;
        float m1 = (r1g < N) ? mask[r1g] : 0.f;
        if (MPOW == 2) { m0 *= m0; m1 *= m1; }
        #pragma unroll
        for (int na = 0; na < 8; na++) {
            int col = wc * 64 + na * 8 + 2 * tg;
            if (r0g < N) {
                __half2 h = __floats2half2_rn(acc[ma][na][0] * m0,
                                              acc[ma][na][1] * m0);
                *(__half2*)(C + (size_t)r0g * 128 + col) = h;
            }
            if (r1g < N) {
                __half2 h = __floats2half2_rn(acc[ma][na][2] * m1,
                                              acc[ma][na][3] * m1);
                *(__half2*)(C + (size_t)r1g * 128 + col) = h;
            }
        }
    }
}

// ---------------------------------------------------------------------------
// Gather (R7 form — empirical best): 2 nodes/warp, 16 lanes/node, 8 cols/lane.
// FUSE_LOGMAP=true applies next-layer log-map and writes fp16; else fp32 out.
// ---------------------------------------------------------------------------
template <bool FUSE_LOGMAP>
__global__ __launch_bounds__(256)
void gather_kernel(const int*    __restrict__ adj,
                   const float*  __restrict__ wgt,
                   const float*  __restrict__ mask,
                   const __half* __restrict__ msg,
                   void* __restrict__ xout,
                   int N) {
    __shared__ int2 pairs[8][2][KK];

    int tid   = threadIdx.x;
    int warp  = tid >> 5;
    int lane  = tid & 31;
    int half  = lane >> 4;
    int hl    = lane & 15;
    int node0 = blockIdx.x * 16 + warp * 2;
    int gnode = node0 + half;

    #pragma unroll
    for (int i = 0; i < 2; i++) {
        int idx = lane + i * 32;
        int h   = idx >> 5;
        int k   = idx & 31;
        int gn  = node0 + h;
        if (gn < N) {
            pairs[warp][h][k].x = adj[(size_t)gn * KK + k];
            pairs[warp][h][k].y = __float_as_int(wgt[(size_t)gn * KK + k]);
        }
    }
    __syncwarp();
    if (gnode >= N) return;

    float acc[8];
    #pragma unroll
    for (int i = 0; i < 8; i++) acc[i] = 0.f;

    #pragma unroll
    for (int k = 0; k < KK; k++) {
        int2 p = pairs[warp][half][k];
        float wk = __int_as_float(p.y);
        uint4 raw = *(const uint4*)(msg + (size_t)p.x * DD + hl * 8);
        float2 f0 = __half22float2(*(__half2*)&raw.x);
        float2 f1 = __half22float2(*(__half2*)&raw.y);
        float2 f2 = __half22float2(*(__half2*)&raw.z);
        float2 f3 = __half22float2(*(__half2*)&raw.w);
        acc[0] = fmaf(wk, f0.x, acc[0]);
        acc[1] = fmaf(wk, f0.y, acc[1]);
        acc[2] = fmaf(wk, f1.x, acc[2]);
        acc[3] = fmaf(wk, f1.y, acc[3]);
        acc[4] = fmaf(wk, f2.x, acc[4]);
        acc[5] = fmaf(wk, f2.y, acc[5]);
        acc[6] = fmaf(wk, f3.x, acc[6]);
        acc[7] = fmaf(wk, f3.y, acc[7]);
    }

    float mk = mask[gnode];
    #pragma unroll
    for (int i = 0; i < 8; i++) acc[i] *= mk;

    float s = 0.f;
    #pragma unroll
    for (int i = 0; i < 8; i++) s = fmaf(acc[i], acc[i], s);
    #pragma unroll
    for (int o = 8; o > 0; o >>= 1) s += __shfl_xor_sync(0xffffffffu, s, o);
    float n  = sqrtf(s);
    float nc = fminf(fmaxf(n, 1e-5f), 15.0f);
    float scale = tanhf(nc) / fmaxf(n, 1e-5f) * mk;

    float x[8];
    #pragma unroll
    for (int i = 0; i < 8; i++) x[i] = fmaxf(acc[i] * scale, 0.f) * mk;

    if (FUSE_LOGMAP) {
        float s2 = 0.f;
        #pragma unroll
        for (int i = 0; i < 8; i++) s2 = fmaf(x[i], x[i], s2);
        #pragma unroll
        for (int o = 8; o > 0; o >>= 1) s2 += __shfl_xor_sync(0xffffffffu, s2, o);
        float n2  = sqrtf(s2);
        float nc2 = fminf(fmaxf(n2, 1e-5f), 1.0f - 1e-5f);
        float ls  = atanhf(nc2) / fmaxf(n2, 1e-5f) * mk;
        #pragma unroll
        for (int i = 0; i < 8; i++) x[i] *= ls;

        __half2 h0 = __floats2half2_rn(x[0], x[1]);
        __half2 h1 = __floats2half2_rn(x[2], x[3]);
        __half2 h2 = __floats2half2_rn(x[4], x[5]);
        __half2 h3 = __floats2half2_rn(x[6], x[7]);
        uint4 u = make_uint4(*(unsigned*)&h0, *(unsigned*)&h1,
                             *(unsigned*)&h2, *(unsigned*)&h3);
        *(uint4*)((__half*)xout + (size_t)gnode * DD + hl * 8) = u;
    } else {
        float* dst = (float*)xout + (size_t)gnode * DD + hl * 8;
        *(float4*)(dst)     = make_float4(x[0], x[1], x[2], x[3]);
        *(float4*)(dst + 4) = make_float4(x[4], x[5], x[6], x[7]);
    }
}

// ---------------------------------------------------------------------------
extern "C" void kernel_launch(void* const* d_in, const int* in_sizes, int n_in,
                              void* d_out, int out_size) {
    const float* node_repr = (const float*)d_in[0];
    const int*   adj       = (const int*)  d_in[1];
    const float* weight    = (const float*)d_in[2];
    const float* mask      = (const float*)d_in[3];
    const float* msg_w     = (const float*)d_in[4];

    int N  = in_sizes[0] / DD;
    int NT = (N + 127) / 128;

    __half*  xbuf;
    __half*  mbuf;
    __half2* whbuf;
    cudaGetSymbolAddress((void**)&xbuf, g_xh);
    cudaGetSymbolAddress((void**)&mbuf, g_msg);
    cudaGetSymbolAddress((void**)&whbuf, g_wh);

    static bool attr_done = false;
    if (!attr_done) {
        cudaFuncSetAttribute(gemm_tc_kernel<float, 2>,
                             cudaFuncAttributeMaxDynamicSharedMemorySize, GEMM_SMEM);
        cudaFuncSetAttribute(gemm_tc_kernel<__half, 1>,
                             cudaFuncAttributeMaxDynamicSharedMemorySize, GEMM_SMEM);
        attr_done = true;
    }

    int gatherBlocks = (N + 15) / 16;

    // Pre-pair both layers' W into half2 (k2-major)
    prep_w_kernel<<<64, 256>>>(msg_w, whbuf);

    // ---- Layer 0 ----  ((x*m)@W*m = m^2*(x@W): mask^2 in epilogue)
    gemm_tc_kernel<float, 2><<<NT, 256, GEMM_SMEM>>>(node_repr, whbuf, mask, mbuf, N);
    gather_kernel<true><<<gatherBlocks, 256>>>(adj, weight, mask, mbuf, xbuf, N);

    // ---- Layer 1 ----  (xbuf fp16, tangent-space * mask)
    gemm_tc_kernel<__half, 1><<<NT, 256, GEMM_SMEM>>>(xbuf, whbuf + 64 * DD, mask, mbuf, N);
    gather_kernel<false><<<gatherBlocks, 256>>>(adj, weight, mask, mbuf, d_out, N);
}